// round 15
// baseline (speedup 1.0000x reference)
#include <cuda_runtime.h>
#include <math.h>
#include <stdint.h>

#define Bq 32
#define Tq 256
#define Nq 256
#define Dq 1024
#define Cq 80

// output layout (float32, tuple order)
#define OFF_BOX    (Bq*Tq*Dq)
#define OFF_ACT    (OFF_BOX + Bq*Tq*4)
#define OFF_AGE    (OFF_ACT + Bq*Tq)
#define OFF_HITS   (OFF_AGE + Bq*Tq)
#define OFF_MATCH  (OFF_HITS + Bq*Tq)
#define OFF_SCORES (OFF_MATCH + Bq*Tq)

// scratch
__device__ float  g_C[Bq*Tq*Nq];      // cost matrix (fallback path)
__device__ float2 g_rmax[Bq*Tq*2];    // per-(row, colTile) max/arg
__device__ int    g_match[Bq*Tq];

// ---------------------------------------------------------------------------
// active-storage-width probe, warp-converged
__device__ __forceinline__ int probe_s4(const unsigned char* __restrict__ act) {
    int lane = threadIdx.x & 31;
    int o1 = (act[4 * lane + 1] != 0) ? 1 : 0;
    int o2 = (act[4 * (lane + 32) + 1] != 0) ? 1 : 0;
    int ones = __popc(__ballot_sync(0xffffffffu, o1)) +
               __popc(__ballot_sync(0xffffffffu, o2));
    return (ones > 8) ? 0 : 1;
}

__device__ __forceinline__ bool get_active(const void* act, int idx, int s4) {
    if (s4) return ((const int*)act)[idx] != 0;
    return ((const unsigned char*)act)[idx] != 0;
}

__device__ __forceinline__ uint32_t smem_u32(const void* p) {
    uint32_t a;
    asm("{ .reg .u64 t; cvta.to.shared.u64 t, %1; cvt.u32.u64 %0, t; }" : "=r"(a) : "l"(p));
    return a;
}

// bf16x2 mma: D(f32x4) += A(bf16 m16k16) * B(bf16 k16n8)
__device__ __forceinline__ void mma16816(float* d, const uint32_t* a, const uint32_t* b) {
    asm volatile(
        "mma.sync.aligned.m16n8k16.row.col.f32.bf16.bf16.f32 "
        "{%0,%1,%2,%3}, {%4,%5,%6,%7}, {%8,%9}, {%0,%1,%2,%3};"
        : "+f"(d[0]), "+f"(d[1]), "+f"(d[2]), "+f"(d[3])
        : "r"(a[0]), "r"(a[1]), "r"(a[2]), "r"(a[3]), "r"(b[0]), "r"(b[1]));
}

__device__ __forceinline__ void ldsm4(uint32_t* r, uint32_t addr) {
    asm volatile("ldmatrix.sync.aligned.m8n8.x4.shared.b16 {%0,%1,%2,%3}, [%4];"
                 : "=r"(r[0]), "=r"(r[1]), "=r"(r[2]), "=r"(r[3]) : "r"(addr));
}

// fp32 float4 -> (hi bf16x2 pair, lo bf16x2 pair)
__device__ __forceinline__ void split4(float4 v, uint32_t& h0, uint32_t& h1,
                                       uint32_t& l0, uint32_t& l1) {
    asm("cvt.rn.bf16x2.f32 %0, %1, %2;" : "=r"(h0) : "f"(v.y), "f"(v.x));
    asm("cvt.rn.bf16x2.f32 %0, %1, %2;" : "=r"(h1) : "f"(v.w), "f"(v.z));
    float rx = v.x - __uint_as_float(h0 << 16);
    float ry = v.y - __uint_as_float(h0 & 0xFFFF0000u);
    float rz = v.z - __uint_as_float(h1 << 16);
    float rw = v.w - __uint_as_float(h1 & 0xFFFF0000u);
    asm("cvt.rn.bf16x2.f32 %0, %1, %2;" : "=r"(l0) : "f"(ry), "f"(rx));
    asm("cvt.rn.bf16x2.f32 %0, %1, %2;" : "=r"(l1) : "f"(rw), "f"(rz));
}

// ---------------------------------------------------------------------------
// HMMA 3-pass split GEMM. 128x128 tile per CTA, 512 threads (16 warps 4x4,
// warp tile 32x32), K chunks of 32, double-buffered, ldmatrix loads.
// Grid = 128 CTAs = one balanced wave on 148 SMs.
#define KST 20              // smem row stride in uint32 (80 B, LDSM conflict-free)
#define STGW (128*KST)      // 2560 words per sub-tile (A or B, hi or lo)
#define OFF_BHI (2*STGW)    // 5120
#define OFF_BLO (3*STGW)    // 7680
#define STAGE (4*STGW)      // 10240 words = 40960 B per stage

__global__ __launch_bounds__(512, 1) void gemm_cmat_mma(
    const float* __restrict__ tm, const float* __restrict__ dm,
    const float* __restrict__ tb, const float* __restrict__ db,
    const void* __restrict__ act) {
    extern __shared__ uint32_t dyn[];
    __shared__ float s_an[128], s_bn[128], s_dinv[128];
    __shared__ float4 s_tbox[128], s_dbox[128];
    __shared__ float2 s_rmv[4][128];

    int tid = threadIdx.x;
    int b = blockIdx.z, rowBase = blockIdx.y * 128, colBase = blockIdx.x * 128;
    int s4 = probe_s4((const unsigned char*)act);

    int r5 = tid >> 2, q4 = tid & 3;         // load role: row 0..127, k-quarter
    const float* aP = tm + ((size_t)(b * Tq + rowBase + r5)) * Dq + q4 * 8;
    const float* bP = dm + ((size_t)(b * Nq + colBase + r5)) * Dq + q4 * 8;
    int kp = r5 * KST + q4 * 4;

    int lane = tid & 31, wid = tid >> 5;
    int wm = wid & 3, wn = wid >> 2;         // warp tile: rows wm*32+, cols wn*32+
    int qrow = lane >> 2, qk = lane & 3;

    // ldmatrix per-lane base addresses (byte offsets within a stage)
    uint32_t sm0 = smem_u32(dyn);
    uint32_t aAddr = sm0 + (uint32_t)(wm * 32 + (lane & 15)) * 80u + (uint32_t)(lane >> 4) * 16u;
    uint32_t bAddr = sm0 + OFF_BHI * 4u
                   + (uint32_t)(wn * 32 + ((lane >> 4) * 8) + (lane & 7)) * 80u
                   + (uint32_t)((lane >> 3) & 1) * 16u;

    float acc[2][4][4];
    #pragma unroll
    for (int mi = 0; mi < 2; mi++)
        #pragma unroll
        for (int ni = 0; ni < 4; ni++)
            #pragma unroll
            for (int q = 0; q < 4; q++) acc[mi][ni][q] = 0.0f;

    float asum = 0.f, bsum = 0.f;

    float4 ra[2], rb[2];
    #pragma unroll
    for (int q = 0; q < 2; q++) {
        ra[q] = *(const float4*)(aP + q * 4);
        rb[q] = *(const float4*)(bP + q * 4);
    }
    // prologue: convert+store chunk 0 into stage 0
    {
        uint32_t* st = dyn;
        #pragma unroll
        for (int q = 0; q < 2; q++) {
            float4 v = ra[q];
            asum += v.x*v.x + v.y*v.y + v.z*v.z + v.w*v.w;
            uint32_t h0,h1,l0,l1; split4(v, h0,h1,l0,l1);
            st[kp + q*2] = h0;           st[kp + q*2 + 1] = h1;
            st[STGW + kp + q*2] = l0;    st[STGW + kp + q*2 + 1] = l1;
            v = rb[q];
            bsum += v.x*v.x + v.y*v.y + v.z*v.z + v.w*v.w;
            split4(v, h0,h1,l0,l1);
            st[OFF_BHI + kp + q*2] = h0; st[OFF_BHI + kp + q*2 + 1] = h1;
            st[OFF_BLO + kp + q*2] = l0; st[OFF_BLO + kp + q*2 + 1] = l1;
        }
    }
    __syncthreads();

    for (int c = 0; c < 32; c++) {
        // prefetch chunk c+1 from global
        if (c < 31) {
            int k0 = (c + 1) * 32;
            #pragma unroll
            for (int q = 0; q < 2; q++) {
                ra[q] = *(const float4*)(aP + k0 + q * 4);
                rb[q] = *(const float4*)(bP + k0 + q * 4);
            }
        }
        // MMA on stage c&1
        {
            uint32_t stg = (uint32_t)(c & 1) * (STAGE * 4u);
            #pragma unroll
            for (int s = 0; s < 2; s++) {
                uint32_t ko = stg + (uint32_t)s * 32u;
                uint32_t ahf[2][4], alf[2][4], bhf[4][2], blf[4][2];
                #pragma unroll
                for (int mi = 0; mi < 2; mi++) {
                    ldsm4(ahf[mi], aAddr + ko + (uint32_t)(mi * 16) * 80u);
                    ldsm4(alf[mi], aAddr + ko + (uint32_t)(mi * 16) * 80u + STGW * 4u);
                }
                #pragma unroll
                for (int pr = 0; pr < 2; pr++) {
                    uint32_t t4[4];
                    ldsm4(t4, bAddr + ko + (uint32_t)(pr * 16) * 80u);
                    bhf[2*pr][0] = t4[0]; bhf[2*pr][1] = t4[1];
                    bhf[2*pr+1][0] = t4[2]; bhf[2*pr+1][1] = t4[3];
                    ldsm4(t4, bAddr + ko + (uint32_t)(pr * 16) * 80u + STGW * 4u);
                    blf[2*pr][0] = t4[0]; blf[2*pr][1] = t4[1];
                    blf[2*pr+1][0] = t4[2]; blf[2*pr+1][1] = t4[3];
                }
                // pass-major order: dependent MMAs on one acc are 8 apart
                #pragma unroll
                for (int mi = 0; mi < 2; mi++)
                    #pragma unroll
                    for (int ni = 0; ni < 4; ni++) mma16816(acc[mi][ni], ahf[mi], bhf[ni]);
                #pragma unroll
                for (int mi = 0; mi < 2; mi++)
                    #pragma unroll
                    for (int ni = 0; ni < 4; ni++) mma16816(acc[mi][ni], ahf[mi], blf[ni]);
                #pragma unroll
                for (int mi = 0; mi < 2; mi++)
                    #pragma unroll
                    for (int ni = 0; ni < 4; ni++) mma16816(acc[mi][ni], alf[mi], bhf[ni]);
            }
        }
        // convert+store chunk c+1 into the other stage
        if (c < 31) {
            uint32_t* st = dyn + ((c + 1) & 1) * STAGE;
            #pragma unroll
            for (int q = 0; q < 2; q++) {
                float4 v = ra[q];
                asum += v.x*v.x + v.y*v.y + v.z*v.z + v.w*v.w;
                uint32_t h0,h1,l0,l1; split4(v, h0,h1,l0,l1);
                st[kp + q*2] = h0;           st[kp + q*2 + 1] = h1;
                st[STGW + kp + q*2] = l0;    st[STGW + kp + q*2 + 1] = l1;
                v = rb[q];
                bsum += v.x*v.x + v.y*v.y + v.z*v.z + v.w*v.w;
                split4(v, h0,h1,l0,l1);
                st[OFF_BHI + kp + q*2] = h0; st[OFF_BHI + kp + q*2 + 1] = h1;
                st[OFF_BLO + kp + q*2] = l0; st[OFF_BLO + kp + q*2 + 1] = l1;
            }
        }
        __syncthreads();
    }

    // norms: 4 lanes (k-quarters) share each row
    asum += __shfl_xor_sync(0xffffffffu, asum, 1);
    asum += __shfl_xor_sync(0xffffffffu, asum, 2);
    bsum += __shfl_xor_sync(0xffffffffu, bsum, 1);
    bsum += __shfl_xor_sync(0xffffffffu, bsum, 2);
    if ((tid & 3) == 0) { s_an[r5] = asum; s_bn[r5] = bsum; }
    if (tid < 128) s_tbox[tid] = ((const float4*)tb)[b * Tq + rowBase + tid];
    else if (tid < 256) s_dbox[tid - 128] = ((const float4*)db)[b * Nq + colBase + tid - 128];
    __syncthreads();
    if (tid < 128) s_dinv[tid] = 1.0f / fmaxf(sqrtf(s_bn[tid]), 1e-12f);
    __syncthreads();

    #pragma unroll
    for (int mi = 0; mi < 2; mi++) {
        #pragma unroll
        for (int half = 0; half < 2; half++) {
            int lr = wm * 32 + mi * 16 + half * 8 + qrow;
            int gt = rowBase + lr;
            float ti = 1.0f / fmaxf(sqrtf(s_an[lr]), 1e-12f);
            float4 tbx = s_tbox[lr];
            bool aa = get_active(act, b * Tq + gt, s4);
            float tx1 = tbx.x - 0.5f * tbx.z, tx2 = tbx.x + 0.5f * tbx.z;
            float ty1 = tbx.y - 0.5f * tbx.w, ty2 = tbx.y + 0.5f * tbx.w;
            float tarea = tbx.z * tbx.w;
            float best = -2.0f; int barg = 0;
            float* dst = g_C + ((size_t)(b * Tq + gt)) * Nq + colBase;
            #pragma unroll
            for (int ni = 0; ni < 4; ni++) {
                int lc = wn * 32 + ni * 8 + qk * 2;
                float2 o;
                #pragma unroll
                for (int j = 0; j < 2; j++) {
                    float dot = acc[mi][ni][half * 2 + j];
                    float4 dv = s_dbox[lc + j];
                    float dx1 = dv.x - 0.5f * dv.z, dx2 = dv.x + 0.5f * dv.z;
                    float dy1 = dv.y - 0.5f * dv.w, dy2 = dv.y + 0.5f * dv.w;
                    float iw = fmaxf(fminf(tx2, dx2) - fmaxf(tx1, dx1), 0.0f);
                    float ih = fmaxf(fminf(ty2, dy2) - fmaxf(ty1, dy1), 0.0f);
                    float inter = iw * ih;
                    float uni = tarea + dv.z * dv.w - inter;
                    float iou = inter / (uni + 1e-6f);
                    float cv = 0.7f * (dot * ti * s_dinv[lc + j]) + 0.3f * iou;
                    cv = aa ? cv : -1.0f;
                    if (cv > best) { best = cv; barg = lc + j; }
                    (&o.x)[j] = cv;
                }
                *(float2*)(dst + lc) = o;
            }
            #pragma unroll
            for (int off = 1; off <= 2; off <<= 1) {
                float ov = __shfl_xor_sync(0xffffffffu, best, off);
                int   oa = __shfl_xor_sync(0xffffffffu, barg, off);
                if (ov > best || (ov == best && oa < barg)) { best = ov; barg = oa; }
            }
            if (qk == 0) s_rmv[wn][lr] = make_float2(best, __int_as_float(colBase + barg));
        }
    }
    __syncthreads();
    if (tid < 128) {
        float2 mm = s_rmv[0][tid];
        #pragma unroll
        for (int w = 1; w < 4; w++) {
            float2 m = s_rmv[w][tid];
            if (m.x > mm.x) mm = m;   // larger col on tie loses (wn ascending = col ascending)
        }
        g_rmax[(b * Tq + rowBase + tid) * 2 + blockIdx.x] = mm;
    }
}

// ---------------------------------------------------------------------------
// Greedy matching, one warp per batch. Fast path reads g_rmax only.
__global__ __launch_bounds__(32) void greedy_kernel() {
    int b = blockIdx.x;
    int l = threadIdx.x;

    float rmax[8]; int rarg[8];
    #pragma unroll
    for (int i = 0; i < 8; i++) {
        int row = i * 32 + l;
        float2 m0 = g_rmax[(b * Tq + row) * 2 + 0];
        float2 m1 = g_rmax[(b * Tq + row) * 2 + 1];
        float v = m0.x; int a = __float_as_int(m0.y);
        if (m1.x > v) { v = m1.x; a = __float_as_int(m1.y); }
        rmax[i] = v; rarg[i] = a;
    }

    // fast-path distinctness check
    unsigned cm[8] = {0,0,0,0,0,0,0,0};
    int cnt = 0;
    #pragma unroll
    for (int i = 0; i < 8; i++)
        if (rmax[i] >= 0.7f) { cnt++; cm[rarg[i] >> 5] |= 1u << (rarg[i] & 31); }
    int lpop = 0;
    #pragma unroll
    for (int w = 0; w < 8; w++) lpop += __popc(cm[w]);
    int totc = __reduce_add_sync(0xffffffffu, cnt);
    int orp = 0;
    #pragma unroll
    for (int w = 0; w < 8; w++) orp += __popc(__reduce_or_sync(0xffffffffu, cm[w]));
    bool dup = (lpop != cnt);
    bool conflict = __any_sync(0xffffffffu, dup) || (orp != totc);

    if (!conflict) {
        #pragma unroll
        for (int i = 0; i < 8; i++)
            g_match[b * Tq + i * 32 + l] = (rmax[i] >= 0.7f) ? rarg[i] : -1;
        return;
    }

    // slow path: exact sequential greedy (value desc, flat-index asc tiebreak)
    #pragma unroll
    for (int i = 0; i < 8; i++) g_match[b * Tq + i * 32 + l] = -1;
    unsigned taken[8] = {0,0,0,0,0,0,0,0};
    for (int it = 0; it < 256; it++) {
        float bv = rmax[0]; int bi = 0;
        #pragma unroll
        for (int i = 1; i < 8; i++) if (rmax[i] > bv) { bv = rmax[i]; bi = i; }
        int brow = bi * 32 + l;
        #pragma unroll
        for (int off = 16; off; off >>= 1) {
            float ov = __shfl_xor_sync(0xffffffffu, bv, off);
            int orow  = __shfl_xor_sync(0xffffffffu, brow, off);
            if (ov > bv || (ov == bv && orow < brow)) { bv = ov; brow = orow; }
        }
        if (bv < 0.7f) break;
        int ol = brow & 31, oi = brow >> 5;
        int d = __shfl_sync(0xffffffffu, rarg[oi], ol);
        taken[d >> 5] |= 1u << (d & 31);
        if (l == ol) { g_match[b * Tq + brow] = d; rmax[oi] = -3.0f; }
        #pragma unroll
        for (int i = 0; i < 8; i++) {
            if (rmax[i] >= 0.7f && rarg[i] == d) {
                int row = i * 32 + l;
                const float* rr = g_C + ((size_t)b * Tq + row) * Nq;
                float best = -2.0f; int arg = 0;
                for (int n = 0; n < 256; n++) {
                    if (taken[n >> 5] & (1u << (n & 31))) continue;
                    float c = rr[n];
                    if (c > best) { best = c; arg = n; }
                }
                rmax[i] = best; rarg[i] = arg;
            }
        }
    }
}

// ---------------------------------------------------------------------------
// Output assembly + scores (fused).
#define NR (Bq*Tq/4)

__global__ __launch_bounds__(256) void output_kernel(
    const float* __restrict__ tm, const float* __restrict__ dm,
    const float* __restrict__ tb, const float* __restrict__ db,
    const void* __restrict__ act, const int* __restrict__ age,
    const int* __restrict__ hits, const float* __restrict__ logits,
    float* __restrict__ out) {
    int blk = blockIdx.x;
    if (blk < NR) {
        int row = blk * 4 + (threadIdx.x >> 6);
        int b = row >> 8;
        int m = g_match[row];
        const float* src = (m >= 0) ? (dm + ((size_t)b * Nq + m) * Dq)
                                    : (tm + (size_t)row * Dq);
        int j = threadIdx.x & 63;
        float4 v0 = ((const float4*)src)[j];
        float4 v1 = ((const float4*)src)[j + 64];
        float4 v2 = ((const float4*)src)[j + 128];
        float4 v3 = ((const float4*)src)[j + 192];
        float4* dst = (float4*)(out + (size_t)row * Dq);
        dst[j] = v0; dst[j + 64] = v1; dst[j + 128] = v2; dst[j + 192] = v3;
    } else if (blk < NR + Bq) {
        int s4 = probe_s4((const unsigned char*)act);
        int b = blk - NR;
        int t = threadIdx.x;
        int idx = b * Tq + t;
        int m = g_match[idx];
        bool matched = m >= 0;
        int d = matched ? m : 0;
        bool a = get_active(act, idx, s4);
        int h = hits[idx] + (matched ? 1 : 0);
        bool unm = a && !matched;
        int ag = age[idx];
        int newage = matched ? 0 : (unm ? ag + 1 : ag);
        bool newact = matched ? true : (unm ? (newage <= 10) : a);
        float4 bx = matched ? ((const float4*)db)[b * Nq + d]
                            : ((const float4*)tb)[idx];
        ((float4*)(out + OFF_BOX))[idx] = bx;
        out[OFF_ACT   + idx] = newact ? 1.0f : 0.0f;
        out[OFF_AGE   + idx] = (float)newage;
        out[OFF_HITS  + idx] = (float)h;
        out[OFF_MATCH + idx] = (float)m;
    } else {
        int row = (blk - NR - Bq) * 8 + (threadIdx.x >> 5);
        int lane = threadIdx.x & 31;
        const float* p = logits + (size_t)row * Cq;
        float a = p[lane];
        float bb = p[lane + 32];
        bool hasc = (lane + 64) < Cq;
        float c = hasc ? p[lane + 64] : -INFINITY;
        float m = fmaxf(a, fmaxf(bb, c));
        #pragma unroll
        for (int off = 16; off; off >>= 1) m = fmaxf(m, __shfl_xor_sync(0xffffffffu, m, off));
        float s = expf(a - m) + expf(bb - m) + (hasc ? expf(c - m) : 0.0f);
        #pragma unroll
        for (int off = 16; off; off >>= 1) s += __shfl_xor_sync(0xffffffffu, s, off);
        if (lane == 0) out[OFF_SCORES + row] = 1.0f / s;
    }
}

// ---------------------------------------------------------------------------
extern "C" void kernel_launch(void* const* d_in, const int* in_sizes, int n_in,
                              void* d_out, int out_size) {
    const float* tm   = (const float*)d_in[0];
    const float* tb   = (const float*)d_in[1];
    const void*  act  = d_in[2];
    const int*   age  = (const int*)d_in[3];
    const int*   hits = (const int*)d_in[4];
    const float* db   = (const float*)d_in[5];
    const float* dm   = (const float*)d_in[6];
    const float* cl   = (const float*)d_in[7];
    float* out = (float*)d_out;

    static int cfg_done = 0;
    int smem_bytes = 2 * STAGE * 4;   // 81920
    if (!cfg_done) {
        cudaFuncSetAttribute(gemm_cmat_mma,
                             cudaFuncAttributeMaxDynamicSharedMemorySize, smem_bytes);
        cfg_done = 1;
    }

    dim3 g(Nq/128, Tq/128, Bq);
    gemm_cmat_mma<<<g, 512, smem_bytes>>>(tm, dm, tb, db, act);
    greedy_kernel<<<Bq, 32>>>();
    output_kernel<<<NR + Bq + (Bq*Nq)/8, 256>>>(tm, dm, tb, db, act, age, hits, cl, out);
}

// round 17
// speedup vs baseline: 1.0764x; 1.0764x over previous
#include <cuda_runtime.h>
#include <math.h>
#include <stdint.h>

#define Bq 32
#define Tq 256
#define Nq 256
#define Dq 1024
#define Cq 80
#define NROW (Bq*Tq)   // 8192 rows per tensor

// output layout (float32, tuple order)
#define OFF_BOX    (Bq*Tq*Dq)
#define OFF_ACT    (OFF_BOX + Bq*Tq*4)
#define OFF_AGE    (OFF_ACT + Bq*Tq)
#define OFF_HITS   (OFF_AGE + Bq*Tq)
#define OFF_MATCH  (OFF_HITS + Bq*Tq)
#define OFF_SCORES (OFF_MATCH + Bq*Tq)

// scratch
__device__ float    g_C[Bq*Tq*Nq];      // cost matrix (fallback path)
__device__ float2   g_rmax[Bq*Tq*4];    // per-(row, colTile) max/arg
__device__ int      g_match[Bq*Tq];
__device__ uint32_t g_Ahi[NROW*512];    // bf16x2 words (track_memory hi)
__device__ uint32_t g_Alo[NROW*512];
__device__ uint32_t g_Bhi[NROW*512];    // det_memory hi
__device__ uint32_t g_Blo[NROW*512];
__device__ float    g_invA[NROW], g_invB[NROW];

// ---------------------------------------------------------------------------
// active-storage-width probe, warp-converged
__device__ __forceinline__ int probe_s4(const unsigned char* __restrict__ act) {
    int lane = threadIdx.x & 31;
    int o1 = (act[4 * lane + 1] != 0) ? 1 : 0;
    int o2 = (act[4 * (lane + 32) + 1] != 0) ? 1 : 0;
    int ones = __popc(__ballot_sync(0xffffffffu, o1)) +
               __popc(__ballot_sync(0xffffffffu, o2));
    return (ones > 8) ? 0 : 1;
}

__device__ __forceinline__ bool get_active(const void* act, int idx, int s4) {
    if (s4) return ((const int*)act)[idx] != 0;
    return ((const unsigned char*)act)[idx] != 0;
}

__device__ __forceinline__ uint32_t smem_u32(const void* p) {
    uint32_t a;
    asm("{ .reg .u64 t; cvta.to.shared.u64 t, %1; cvt.u32.u64 %0, t; }" : "=r"(a) : "l"(p));
    return a;
}

// bf16x2 mma: D(f32x4) += A(bf16 m16k16) * B(bf16 k16n8)
__device__ __forceinline__ void mma16816(float* d, const uint32_t* a, const uint32_t* b) {
    asm volatile(
        "mma.sync.aligned.m16n8k16.row.col.f32.bf16.bf16.f32 "
        "{%0,%1,%2,%3}, {%4,%5,%6,%7}, {%8,%9}, {%0,%1,%2,%3};"
        : "+f"(d[0]), "+f"(d[1]), "+f"(d[2]), "+f"(d[3])
        : "r"(a[0]), "r"(a[1]), "r"(a[2]), "r"(a[3]), "r"(b[0]), "r"(b[1]));
}

__device__ __forceinline__ void ldsm4(uint32_t* r, uint32_t addr) {
    asm volatile("ldmatrix.sync.aligned.m8n8.x4.shared.b16 {%0,%1,%2,%3}, [%4];"
                 : "=r"(r[0]), "=r"(r[1]), "=r"(r[2]), "=r"(r[3]) : "r"(addr));
}

// fp32 float4 -> (hi bf16x2 pair, lo bf16x2 pair)
__device__ __forceinline__ void split4(float4 v, uint32_t& h0, uint32_t& h1,
                                       uint32_t& l0, uint32_t& l1) {
    asm("cvt.rn.bf16x2.f32 %0, %1, %2;" : "=r"(h0) : "f"(v.y), "f"(v.x));
    asm("cvt.rn.bf16x2.f32 %0, %1, %2;" : "=r"(h1) : "f"(v.w), "f"(v.z));
    float rx = v.x - __uint_as_float(h0 << 16);
    float ry = v.y - __uint_as_float(h0 & 0xFFFF0000u);
    float rz = v.z - __uint_as_float(h1 << 16);
    float rw = v.w - __uint_as_float(h1 & 0xFFFF0000u);
    asm("cvt.rn.bf16x2.f32 %0, %1, %2;" : "=r"(l0) : "f"(ry), "f"(rx));
    asm("cvt.rn.bf16x2.f32 %0, %1, %2;" : "=r"(l1) : "f"(rw), "f"(rz));
}

// ---------------------------------------------------------------------------
// One-shot fp32 -> bf16 hi/lo split + row inverse-norms. One block per row.
__global__ __launch_bounds__(256) void split_kernel(const float* __restrict__ tm,
                                                    const float* __restrict__ dm) {
    int row = blockIdx.x;
    bool isA = row < NROW;
    int r = isA ? row : row - NROW;
    const float* src = (isA ? tm : dm) + (size_t)r * Dq;
    uint2* hi = (uint2*)((isA ? g_Ahi : g_Bhi) + (size_t)r * 512);
    uint2* lo = (uint2*)((isA ? g_Alo : g_Blo) + (size_t)r * 512);
    int t = threadIdx.x;
    float4 v = ((const float4*)src)[t];
    float s = v.x*v.x + v.y*v.y + v.z*v.z + v.w*v.w;
    uint32_t h0, h1, l0, l1;
    split4(v, h0, h1, l0, l1);
    hi[t] = make_uint2(h0, h1);
    lo[t] = make_uint2(l0, l1);
    __shared__ float red[8];
    #pragma unroll
    for (int off = 16; off; off >>= 1) s += __shfl_down_sync(0xffffffffu, s, off);
    if ((t & 31) == 0) red[t >> 5] = s;
    __syncthreads();
    if (t < 8) {
        float x = red[t];
        #pragma unroll
        for (int off = 4; off; off >>= 1) x += __shfl_down_sync(0xffu, x, off);
        if (t == 0) (isA ? g_invA : g_invB)[r] = 1.0f / fmaxf(sqrtf(x), 1e-12f);
    }
}

// ---------------------------------------------------------------------------
// HMMA 3-pass split GEMM over pre-split bf16 inputs. 128x64 tile per CTA
// (2 CTAs/SM), K chunks of 32, 8 warps 4x2 (warp tile 32x32), double-buffered,
// ldmatrix fragment loads. No conversion in the loop.
#define KST 20              // smem row stride in uint32 (80 B)
#define STGW_A (128*KST)    // 2560 words per A sub-tile
#define STGW_B (64*KST)     // 1280 words per B sub-tile
#define OFF_BHI (2*STGW_A)            // 5120
#define OFF_BLO (2*STGW_A + STGW_B)   // 6400
#define STAGE (2*STGW_A + 2*STGW_B)   // 7680 words = 30720 B

__global__ __launch_bounds__(256, 2) void gemm_cmat_mma(
    const float* __restrict__ tb, const float* __restrict__ db,
    const void* __restrict__ act) {
    extern __shared__ uint32_t dyn[];
    __shared__ float s_tinv[128], s_dinv[64];
    __shared__ float4 s_tbox[128], s_dbox[64];
    __shared__ float2 s_rmv[2][128];

    int tid = threadIdx.x;
    int b = blockIdx.z, rowBase = blockIdx.y * 128, colBase = blockIdx.x * 64;
    int s4 = probe_s4((const unsigned char*)act);

    int ar = tid >> 1, ah_ = tid & 1;        // A load: row 0..127, k-half (16 elems)
    int br = tid >> 2, bq = tid & 3;         // B load: row 0..63, k-quarter (8 elems)
    const uint32_t* aHp = g_Ahi + (size_t)(b * Tq + rowBase + ar) * 512 + ah_ * 8;
    const uint32_t* aLp = g_Alo + (size_t)(b * Tq + rowBase + ar) * 512 + ah_ * 8;
    const uint32_t* bHp = g_Bhi + (size_t)(b * Nq + colBase + br) * 512 + bq * 4;
    const uint32_t* bLp = g_Blo + (size_t)(b * Nq + colBase + br) * 512 + bq * 4;
    int kpa = ar * KST + ah_ * 8;
    int kpb = br * KST + bq * 4;

    int lane = tid & 31, wid = tid >> 5;
    int wm = wid & 3, wn = wid >> 2;         // warp tile: rows wm*32+, cols wn*32+
    int qrow = lane >> 2, qk = lane & 3;

    // ldmatrix per-lane base addresses (byte offsets within a stage)
    uint32_t sm0 = smem_u32(dyn);
    uint32_t aAddr = sm0 + (uint32_t)(wm * 32 + (lane & 15)) * 80u + (uint32_t)(lane >> 4) * 16u;
    uint32_t bAddr = sm0 + OFF_BHI * 4u
                   + (uint32_t)(wn * 32 + ((lane >> 4) * 8) + (lane & 7)) * 80u
                   + (uint32_t)((lane >> 3) & 1) * 16u;

    float acc[2][4][4];
    #pragma unroll
    for (int mi = 0; mi < 2; mi++)
        #pragma unroll
        for (int ni = 0; ni < 4; ni++)
            #pragma unroll
            for (int q = 0; q < 4; q++) acc[mi][ni][q] = 0.0f;

    uint4 pah0, pah1, pal0, pal1, pbh, pbl;
    pah0 = *(const uint4*)(aHp);     pah1 = *(const uint4*)(aHp + 4);
    pal0 = *(const uint4*)(aLp);     pal1 = *(const uint4*)(aLp + 4);
    pbh  = *(const uint4*)(bHp);     pbl  = *(const uint4*)(bLp);

    // prologue: store chunk 0 into stage 0
    {
        uint32_t* st = dyn;
        *(uint4*)&st[kpa] = pah0;              *(uint4*)&st[kpa + 4] = pah1;
        *(uint4*)&st[STGW_A + kpa] = pal0;     *(uint4*)&st[STGW_A + kpa + 4] = pal1;
        *(uint4*)&st[OFF_BHI + kpb] = pbh;     *(uint4*)&st[OFF_BLO + kpb] = pbl;
    }
    __syncthreads();

    for (int c = 0; c < 32; c++) {
        // prefetch chunk c+1 (bf16, 16 words per chunk per row)
        if (c < 31) {
            int k0w = (c + 1) * 16;
            pah0 = *(const uint4*)(aHp + k0w);     pah1 = *(const uint4*)(aHp + k0w + 4);
            pal0 = *(const uint4*)(aLp + k0w);     pal1 = *(const uint4*)(aLp + k0w + 4);
            pbh  = *(const uint4*)(bHp + k0w);     pbl  = *(const uint4*)(bLp + k0w);
        }
        // MMA on stage c&1
        {
            uint32_t stg = (uint32_t)(c & 1) * (STAGE * 4u);
            #pragma unroll
            for (int s = 0; s < 2; s++) {
                uint32_t ko = stg + (uint32_t)s * 32u;
                uint32_t ahf[2][4], alf[2][4], bhf[4][2], blf[4][2];
                #pragma unroll
                for (int mi = 0; mi < 2; mi++) {
                    ldsm4(ahf[mi], aAddr + ko + (uint32_t)(mi * 16) * 80u);
                    ldsm4(alf[mi], aAddr + ko + (uint32_t)(mi * 16) * 80u + STGW_A * 4u);
                }
                #pragma unroll
                for (int pr = 0; pr < 2; pr++) {
                    uint32_t t4[4];
                    ldsm4(t4, bAddr + ko + (uint32_t)(pr * 16) * 80u);
                    bhf[2*pr][0] = t4[0]; bhf[2*pr][1] = t4[1];
                    bhf[2*pr+1][0] = t4[2]; bhf[2*pr+1][1] = t4[3];
                    ldsm4(t4, bAddr + ko + (uint32_t)(pr * 16) * 80u + STGW_B * 4u);
                    blf[2*pr][0] = t4[0]; blf[2*pr][1] = t4[1];
                    blf[2*pr+1][0] = t4[2]; blf[2*pr+1][1] = t4[3];
                }
                // pass-major order: dependent MMAs on one acc are 8 apart
                #pragma unroll
                for (int mi = 0; mi < 2; mi++)
                    #pragma unroll
                    for (int ni = 0; ni < 4; ni++) mma16816(acc[mi][ni], ahf[mi], bhf[ni]);
                #pragma unroll
                for (int mi = 0; mi < 2; mi++)
                    #pragma unroll
                    for (int ni = 0; ni < 4; ni++) mma16816(acc[mi][ni], ahf[mi], blf[ni]);
                #pragma unroll
                for (int mi = 0; mi < 2; mi++)
                    #pragma unroll
                    for (int ni = 0; ni < 4; ni++) mma16816(acc[mi][ni], alf[mi], bhf[ni]);
            }
        }
        // store chunk c+1 into the other stage
        if (c < 31) {
            uint32_t* st = dyn + ((c + 1) & 1) * STAGE;
            *(uint4*)&st[kpa] = pah0;              *(uint4*)&st[kpa + 4] = pah1;
            *(uint4*)&st[STGW_A + kpa] = pal0;     *(uint4*)&st[STGW_A + kpa + 4] = pal1;
            *(uint4*)&st[OFF_BHI + kpb] = pbh;     *(uint4*)&st[OFF_BLO + kpb] = pbl;
        }
        __syncthreads();
    }

    // epilogue aux loads (norms precomputed by split_kernel)
    if (tid < 128) {
        s_tbox[tid] = ((const float4*)tb)[b * Tq + rowBase + tid];
        s_tinv[tid] = g_invA[b * Tq + rowBase + tid];
    } else if (tid < 192) {
        s_dbox[tid - 128] = ((const float4*)db)[b * Nq + colBase + tid - 128];
        s_dinv[tid - 128] = g_invB[b * Nq + colBase + tid - 128];
    }
    __syncthreads();

    #pragma unroll
    for (int mi = 0; mi < 2; mi++) {
        #pragma unroll
        for (int half = 0; half < 2; half++) {
            int lr = wm * 32 + mi * 16 + half * 8 + qrow;
            int gt = rowBase + lr;
            float ti = s_tinv[lr];
            float4 tbx = s_tbox[lr];
            bool aa = get_active(act, b * Tq + gt, s4);
            float tx1 = tbx.x - 0.5f * tbx.z, tx2 = tbx.x + 0.5f * tbx.z;
            float ty1 = tbx.y - 0.5f * tbx.w, ty2 = tbx.y + 0.5f * tbx.w;
            float tarea = tbx.z * tbx.w;
            float best = -2.0f; int barg = 0;
            float* dst = g_C + ((size_t)(b * Tq + gt)) * Nq + colBase;
            #pragma unroll
            for (int ni = 0; ni < 4; ni++) {
                int lc = wn * 32 + ni * 8 + qk * 2;
                float2 o;
                #pragma unroll
                for (int j = 0; j < 2; j++) {
                    float dot = acc[mi][ni][half * 2 + j];
                    float4 dv = s_dbox[lc + j];
                    float dx1 = dv.x - 0.5f * dv.z, dx2 = dv.x + 0.5f * dv.z;
                    float dy1 = dv.y - 0.5f * dv.w, dy2 = dv.y + 0.5f * dv.w;
                    float iw = fmaxf(fminf(tx2, dx2) - fmaxf(tx1, dx1), 0.0f);
                    float ih = fmaxf(fminf(ty2, dy2) - fmaxf(ty1, dy1), 0.0f);
                    float inter = iw * ih;
                    float uni = tarea + dv.z * dv.w - inter;
                    float iou = inter / (uni + 1e-6f);
                    float cv = 0.7f * (dot * ti * s_dinv[lc + j]) + 0.3f * iou;
                    cv = aa ? cv : -1.0f;
                    if (cv > best) { best = cv; barg = lc + j; }
                    (&o.x)[j] = cv;
                }
                *(float2*)(dst + lc) = o;
            }
            #pragma unroll
            for (int off = 1; off <= 2; off <<= 1) {
                float ov = __shfl_xor_sync(0xffffffffu, best, off);
                int   oa = __shfl_xor_sync(0xffffffffu, barg, off);
                if (ov > best || (ov == best && oa < barg)) { best = ov; barg = oa; }
            }
            if (qk == 0) s_rmv[wn][lr] = make_float2(best, __int_as_float(colBase + barg));
        }
    }
    __syncthreads();
    if (tid < 128) {
        float2 m0 = s_rmv[0][tid], m1 = s_rmv[1][tid];
        float2 mm = (m1.x > m0.x) ? m1 : m0;
        g_rmax[(b * Tq + rowBase + tid) * 4 + blockIdx.x] = mm;
    }
}

// ---------------------------------------------------------------------------
// Greedy matching, one warp per batch. Fast path reads g_rmax only.
__global__ __launch_bounds__(32) void greedy_kernel() {
    int b = blockIdx.x;
    int l = threadIdx.x;

    float rmax[8]; int rarg[8];
    #pragma unroll
    for (int i = 0; i < 8; i++) {
        int row = i * 32 + l;
        float v = -3.0f; int a = 0;
        #pragma unroll
        for (int t = 0; t < 4; t++) {
            float2 m = g_rmax[(b * Tq + row) * 4 + t];
            if (m.x > v) { v = m.x; a = __float_as_int(m.y); }
        }
        rmax[i] = v; rarg[i] = a;
    }

    // fast-path distinctness check
    unsigned cm[8] = {0,0,0,0,0,0,0,0};
    int cnt = 0;
    #pragma unroll
    for (int i = 0; i < 8; i++)
        if (rmax[i] >= 0.7f) { cnt++; cm[rarg[i] >> 5] |= 1u << (rarg[i] & 31); }
    int lpop = 0;
    #pragma unroll
    for (int w = 0; w < 8; w++) lpop += __popc(cm[w]);
    int totc = __reduce_add_sync(0xffffffffu, cnt);
    int orp = 0;
    #pragma unroll
    for (int w = 0; w < 8; w++) orp += __popc(__reduce_or_sync(0xffffffffu, cm[w]));
    bool dup = (lpop != cnt);
    bool conflict = __any_sync(0xffffffffu, dup) || (orp != totc);

    if (!conflict) {
        #pragma unroll
        for (int i = 0; i < 8; i++)
            g_match[b * Tq + i * 32 + l] = (rmax[i] >= 0.7f) ? rarg[i] : -1;
        return;
    }

    // slow path: exact sequential greedy (value desc, flat-index asc tiebreak)
    #pragma unroll
    for (int i = 0; i < 8; i++) g_match[b * Tq + i * 32 + l] = -1;
    unsigned taken[8] = {0,0,0,0,0,0,0,0};
    for (int it = 0; it < 256; it++) {
        float bv = rmax[0]; int bi = 0;
        #pragma unroll
        for (int i = 1; i < 8; i++) if (rmax[i] > bv) { bv = rmax[i]; bi = i; }
        int brow = bi * 32 + l;
        #pragma unroll
        for (int off = 16; off; off >>= 1) {
            float ov = __shfl_xor_sync(0xffffffffu, bv, off);
            int orow  = __shfl_xor_sync(0xffffffffu, brow, off);
            if (ov > bv || (ov == bv && orow < brow)) { bv = ov; brow = orow; }
        }
        if (bv < 0.7f) break;
        int ol = brow & 31, oi = brow >> 5;
        int d = __shfl_sync(0xffffffffu, rarg[oi], ol);
        taken[d >> 5] |= 1u << (d & 31);
        if (l == ol) { g_match[b * Tq + brow] = d; rmax[oi] = -3.0f; }
        #pragma unroll
        for (int i = 0; i < 8; i++) {
            if (rmax[i] >= 0.7f && rarg[i] == d) {
                int row = i * 32 + l;
                const float* rr = g_C + ((size_t)b * Tq + row) * Nq;
                float best = -2.0f; int arg = 0;
                for (int n = 0; n < 256; n++) {
                    if (taken[n >> 5] & (1u << (n & 31))) continue;
                    float c = rr[n];
                    if (c > best) { best = c; arg = n; }
                }
                rmax[i] = best; rarg[i] = arg;
            }
        }
    }
}

// ---------------------------------------------------------------------------
// Output assembly + scores (fused).
#define NR (Bq*Tq/4)

__global__ __launch_bounds__(256) void output_kernel(
    const float* __restrict__ tm, const float* __restrict__ dm,
    const float* __restrict__ tb, const float* __restrict__ db,
    const void* __restrict__ act, const int* __restrict__ age,
    const int* __restrict__ hits, const float* __restrict__ logits,
    float* __restrict__ out) {
    int blk = blockIdx.x;
    if (blk < NR) {
        int row = blk * 4 + (threadIdx.x >> 6);
        int b = row >> 8;
        int m = g_match[row];
        const float* src = (m >= 0) ? (dm + ((size_t)b * Nq + m) * Dq)
                                    : (tm + (size_t)row * Dq);
        int j = threadIdx.x & 63;
        float4 v0 = ((const float4*)src)[j];
        float4 v1 = ((const float4*)src)[j + 64];
        float4 v2 = ((const float4*)src)[j + 128];
        float4 v3 = ((const float4*)src)[j + 192];
        float4* dst = (float4*)(out + (size_t)row * Dq);
        dst[j] = v0; dst[j + 64] = v1; dst[j + 128] = v2; dst[j + 192] = v3;
    } else if (blk < NR + Bq) {
        int s4 = probe_s4((const unsigned char*)act);
        int b = blk - NR;
        int t = threadIdx.x;
        int idx = b * Tq + t;
        int m = g_match[idx];
        bool matched = m >= 0;
        int d = matched ? m : 0;
        bool a = get_active(act, idx, s4);
        int h = hits[idx] + (matched ? 1 : 0);
        bool unm = a && !matched;
        int ag = age[idx];
        int newage = matched ? 0 : (unm ? ag + 1 : ag);
        bool newact = matched ? true : (unm ? (newage <= 10) : a);
        float4 bx = matched ? ((const float4*)db)[b * Nq + d]
                            : ((const float4*)tb)[idx];
        ((float4*)(out + OFF_BOX))[idx] = bx;
        out[OFF_ACT   + idx] = newact ? 1.0f : 0.0f;
        out[OFF_AGE   + idx] = (float)newage;
        out[OFF_HITS  + idx] = (float)h;
        out[OFF_MATCH + idx] = (float)m;
    } else {
        int row = (blk - NR - Bq) * 8 + (threadIdx.x >> 5);
        int lane = threadIdx.x & 31;
        const float* p = logits + (size_t)row * Cq;
        float a = p[lane];
        float bb = p[lane + 32];
        bool hasc = (lane + 64) < Cq;
        float c = hasc ? p[lane + 64] : -INFINITY;
        float m = fmaxf(a, fmaxf(bb, c));
        #pragma unroll
        for (int off = 16; off; off >>= 1) m = fmaxf(m, __shfl_xor_sync(0xffffffffu, m, off));
        float s = expf(a - m) + expf(bb - m) + (hasc ? expf(c - m) : 0.0f);
        #pragma unroll
        for (int off = 16; off; off >>= 1) s += __shfl_xor_sync(0xffffffffu, s, off);
        if (lane == 0) out[OFF_SCORES + row] = 1.0f / s;
    }
}

// ---------------------------------------------------------------------------
extern "C" void kernel_launch(void* const* d_in, const int* in_sizes, int n_in,
                              void* d_out, int out_size) {
    const float* tm   = (const float*)d_in[0];
    const float* tb   = (const float*)d_in[1];
    const void*  act  = d_in[2];
    const int*   age  = (const int*)d_in[3];
    const int*   hits = (const int*)d_in[4];
    const float* db   = (const float*)d_in[5];
    const float* dm   = (const float*)d_in[6];
    const float* cl   = (const float*)d_in[7];
    float* out = (float*)d_out;

    static int cfg_done = 0;
    int smem_bytes = 2 * STAGE * 4;   // 61440
    if (!cfg_done) {
        cudaFuncSetAttribute(gemm_cmat_mma,
                             cudaFuncAttributeMaxDynamicSharedMemorySize, smem_bytes);
        cfg_done = 1;
    }

    split_kernel<<<2 * NROW, 256>>>(tm, dm);
    dim3 g(Nq/64, Tq/128, Bq);
    gemm_cmat_mma<<<g, 256, smem_bytes>>>(tb, db, act);
    greedy_kernel<<<Bq, 32>>>();
    output_kernel<<<NR + Bq + (Bq*Nq)/8, 256>>>(tm, dm, tb, db, act, age, hits, cl, out);
}